// round 15
// baseline (speedup 1.0000x reference)
#include <cuda_runtime.h>
#include <cuda_fp16.h>
#include <cstdint>

#define MAX_N   50000
#define MAX_E   800000
#define HID     128
#define KCHUNK  64
#define ROWS_PB 32            // rows per GEMM block (4 warps x 8 rows)
#define SCAN_BS 256

typedef unsigned long long ull;

// ---------------- scratch (device globals; no allocation allowed) ----------
// Activations stored as fp16 (payload compression for the gathers);
// all arithmetic (GEMM accumulate, gather accumulate) stays fp32.
__device__ __align__(16) __half g_h1[MAX_N * HID];    // x @ W1 (fp16, unscaled)
__device__ __align__(16) float  g_agg1[MAX_N * HID];  // layer-1 aggregate (fp32)
__device__ __align__(16) __half g_h2[MAX_N * HID];    // (relu(agg1)@W2)*dis (fp16)
__device__ int   g_deg[MAX_N];
__device__ int   g_off[MAX_N + 1];
__device__ int   g_cnt[MAX_N];
__device__ __align__(16) int g_csr_src[MAX_E];
__device__ float g_dis[MAX_N];
__device__ int   g_bsum[512];
__device__ int   g_boff[512];
__device__ int   g_is_i64;

// ---------------- prep0: zero counters + dtype detect (fused) --------------
__global__ void prep0_kernel(const int* __restrict__ ei, int E, int n) {
    int i = blockIdx.x * blockDim.x + threadIdx.x;
    if (i < n) { g_deg[i] = 0; g_cnt[i] = 0; }
    if (blockIdx.x == 0) {
        __shared__ int nz;
        if (threadIdx.x == 0) nz = 0;
        __syncthreads();
        int cnt = min(E, 2048);
        for (int j = threadIdx.x; j < cnt; j += blockDim.x)
            if (ei[2 * j + 1] != 0) nz = 1;
        __syncthreads();
        if (threadIdx.x == 0) g_is_i64 = nz ? 0 : 1;
    }
}

__device__ __forceinline__ int edge_src(const int* p, int e, int E) {
    return g_is_i64 ? p[2 * e] : p[e];
}
__device__ __forceinline__ int edge_dst(const int* p, int e, int E) {
    return g_is_i64 ? p[2 * E + 2 * e] : p[E + e];
}

// ---------------- degree count ----------------------------------------------
__global__ void count_deg_kernel(const int* __restrict__ ei, int E, int n) {
    int e = blockIdx.x * blockDim.x + threadIdx.x;
    if (e < E) {
        int dst = edge_dst(ei, e, E);
        if ((unsigned)dst < (unsigned)n) atomicAdd(&g_deg[dst], 1);
    }
}

// ---------------- dis + per-block sums (scan phase A) ------------------------
__global__ void dis_scanA_kernel(int n) {
    __shared__ int s[SCAN_BS];
    int t = threadIdx.x;
    int i = blockIdx.x * SCAN_BS + t;
    int v = (i < n) ? g_deg[i] : 0;
    if (i < n) g_dis[i] = rsqrtf(1.0f + (float)v);
    s[t] = v;
    __syncthreads();
    for (int off = SCAN_BS / 2; off > 0; off >>= 1) {
        if (t < off) s[t] += s[t + off];
        __syncthreads();
    }
    if (t == 0) g_bsum[blockIdx.x] = s[0];
}

__global__ void scan_phaseB(int nblocks, int n) {
    __shared__ int s[512];
    int t = threadIdx.x;
    s[t] = (t < nblocks) ? g_bsum[t] : 0;
    __syncthreads();
    #pragma unroll
    for (int off = 1; off < 512; off <<= 1) {
        int add = (t >= off) ? s[t - off] : 0;
        __syncthreads();
        s[t] += add;
        __syncthreads();
    }
    if (t < nblocks) g_boff[t] = s[t] - g_bsum[t];
    if (t == 511) g_off[n] = s[511];
}

__global__ void scan_phaseC(int n) {
    __shared__ int s[SCAN_BS];
    int t = threadIdx.x;
    int i = blockIdx.x * SCAN_BS + t;
    int v = (i < n) ? g_deg[i] : 0;
    s[t] = v;
    __syncthreads();
    #pragma unroll
    for (int off = 1; off < SCAN_BS; off <<= 1) {
        int add = (t >= off) ? s[t - off] : 0;
        __syncthreads();
        s[t] += add;
        __syncthreads();
    }
    if (i < n) g_off[i] = g_boff[blockIdx.x] + s[t] - v;
}

__global__ void fill_csr_kernel(const int* __restrict__ ei, int E, int n) {
    int e = blockIdx.x * blockDim.x + threadIdx.x;
    if (e >= E) return;
    int src = edge_src(ei, e, E);
    int dst = edge_dst(ei, e, E);
    if ((unsigned)src >= (unsigned)n || (unsigned)dst >= (unsigned)n) return;
    int pos = g_off[dst] + atomicAdd(&g_cnt[dst], 1);
    g_csr_src[pos] = src;
}

// ---------------- packed f32x2 FMA helper -----------------------------------
__device__ __forceinline__ void ffma2(ull& acc, ull a, ull b) {
    asm("fma.rn.f32x2 %0, %1, %2, %0;" : "+l"(acc) : "l"(a), "l"(b));
}

// ---------------- GEMM over row range [r_base, r_end), fp16 output ----------
template <bool RELU_IN, int SRC, int DST, bool PRESCALE>
__global__ void gemm_kernel(const float* __restrict__ X,
                            const float* __restrict__ W,
                            int r_base, int r_end, int K) {
    __shared__ __align__(16) float Ws[KCHUNK * HID];        // 32 KB
    __shared__ __align__(16) float2 Xs2[ROWS_PB * KCHUNK];  // 16 KB
    const float* Xp = (SRC == 0) ? X    : g_agg1;
    __half*      Hp = (DST == 0) ? g_h1 : g_h2;

    int t     = threadIdx.x;
    int lane  = t & 31;
    int warp  = t >> 5;
    int wrow0 = warp * 8;
    int r0    = r_base + blockIdx.x * ROWS_PB;

    ull acc0[8], acc1[8];
    #pragma unroll
    for (int r = 0; r < 8; r++) { acc0[r] = 0ull; acc1[r] = 0ull; }

    const ull* Wsu = reinterpret_cast<const ull*>(Ws);
    const ull* Xsu = reinterpret_cast<const ull*>(Xs2);

    for (int k0 = 0; k0 < K; k0 += KCHUNK) {
        int kc = min(KCHUNK, K - k0);
        {
            const float4* Wg = reinterpret_cast<const float4*>(W + (size_t)k0 * HID);
            float4* Wd = reinterpret_cast<float4*>(Ws);
            int nv = kc * HID / 4;
            for (int i = t; i < nv; i += blockDim.x) Wd[i] = Wg[i];
        }
        for (int i = t; i < ROWS_PB * kc; i += blockDim.x) {
            int r = i / kc, k = i % kc;
            float v = (r0 + r < r_end) ? Xp[(size_t)(r0 + r) * K + k0 + k] : 0.0f;
            if (RELU_IN) v = fmaxf(v, 0.0f);
            Xs2[r * KCHUNK + k] = make_float2(v, v);
        }
        __syncthreads();
        for (int k = 0; k < kc; k++) {
            ull w01 = Wsu[(k * HID) / 2 + lane * 2];
            ull w23 = Wsu[(k * HID) / 2 + lane * 2 + 1];
            #pragma unroll
            for (int r = 0; r < 8; r++) {
                ull xv = Xsu[(wrow0 + r) * KCHUNK + k];
                ffma2(acc0[r], xv, w01);
                ffma2(acc1[r], xv, w23);
            }
        }
        __syncthreads();
    }
    #pragma unroll
    for (int r = 0; r < 8; r++) {
        int row = r0 + wrow0 + r;
        if (row < r_end) {
            float d = PRESCALE ? g_dis[row] : 1.0f;
            float2 p0 = *reinterpret_cast<float2*>(&acc0[r]);
            float2 p1 = *reinterpret_cast<float2*>(&acc1[r]);
            __half2 lo = __floats2half2_rn(p0.x * d, p0.y * d);
            __half2 hi = __floats2half2_rn(p1.x * d, p1.y * d);
            uint2 packed;
            packed.x = *reinterpret_cast<unsigned int*>(&lo);
            packed.y = *reinterpret_cast<unsigned int*>(&hi);
            *reinterpret_cast<uint2*>(Hp + (size_t)row * HID + lane * 4) = packed;
        }
    }
}

// ---------------- fp16 2-element load helper ---------------------------------
__device__ __forceinline__ float2 ld_h2(const __half* p) {
    unsigned raw = *reinterpret_cast<const unsigned*>(p);
    __half2 h = *reinterpret_cast<const __half2*>(&raw);
    return __half22float2(h);
}

// ---------------- CSR gather: 2 warps per node (column split) ----------------
// Warp w of node i owns columns [ (w&1)*64, (w&1)*64+64 ); each lane holds
// 2 columns as a float2 accumulator. Payload per warp per edge = 128 B
// (32 lanes x 4 B, contiguous). Doubles memory-level parallelism per node.
template <int SRC, bool RELU_OUT, bool PRESCALED>
__global__ void gather_kernel(const float* __restrict__ b,
                              float* __restrict__ out_ptr, int n) {
    int gw   = (blockIdx.x * blockDim.x + threadIdx.x) >> 5;
    int node = gw >> 1;
    int lane = threadIdx.x & 31;
    if (node >= n) return;
    int col  = (gw & 1) * 64 + lane * 2;          // 2 columns per lane
    const __half* h   = (SRC == 0) ? g_h1   : g_h2;
    float*        agg = (SRC == 0) ? g_agg1 : out_ptr;

    float di  = g_dis[node];
    int   beg = g_off[node];
    int   end = g_off[node + 1];

    const float2 sv = ld_h2(h + (size_t)node * HID + col);
    float sw = PRESCALED ? 1.0f : di;
    float ax = sv.x * sw, ay = sv.y * sw;

    int j = beg;
    // prologue: align j to a multiple of 4 for vectorized index loads
    int a_end = min(end, (beg + 3) & ~3);
    for (; j < a_end; j++) {
        int s0 = g_csr_src[j];
        const float2 v0 = ld_h2(h + (size_t)s0 * HID + col);
        if (PRESCALED) {
            ax += v0.x; ay += v0.y;
        } else {
            float n0 = g_dis[s0];
            ax = fmaf(v0.x, n0, ax); ay = fmaf(v0.y, n0, ay);
        }
    }
    // main loop: one int4 index load per 4 edges
    for (; j + 4 <= end; j += 4) {
        const int4 iv = *reinterpret_cast<const int4*>(g_csr_src + j);
        int s0 = iv.x, s1 = iv.y, s2 = iv.z, s3 = iv.w;
        const float2 v0 = ld_h2(h + (size_t)s0 * HID + col);
        const float2 v1 = ld_h2(h + (size_t)s1 * HID + col);
        const float2 v2 = ld_h2(h + (size_t)s2 * HID + col);
        const float2 v3 = ld_h2(h + (size_t)s3 * HID + col);
        if (PRESCALED) {
            ax += v0.x + v1.x + v2.x + v3.x;
            ay += v0.y + v1.y + v2.y + v3.y;
        } else {
            float n0 = g_dis[s0], n1 = g_dis[s1], n2 = g_dis[s2], n3 = g_dis[s3];
            ax = fmaf(v0.x, n0, ax); ay = fmaf(v0.y, n0, ay);
            ax = fmaf(v1.x, n1, ax); ay = fmaf(v1.y, n1, ay);
            ax = fmaf(v2.x, n2, ax); ay = fmaf(v2.y, n2, ay);
            ax = fmaf(v3.x, n3, ax); ay = fmaf(v3.y, n3, ay);
        }
    }
    // epilogue remainder
    for (; j < end; j++) {
        int s0 = g_csr_src[j];
        const float2 v0 = ld_h2(h + (size_t)s0 * HID + col);
        if (PRESCALED) {
            ax += v0.x; ay += v0.y;
        } else {
            float n0 = g_dis[s0];
            ax = fmaf(v0.x, n0, ax); ay = fmaf(v0.y, n0, ay);
        }
    }

    const float2 bv = *reinterpret_cast<const float2*>(b + col);
    ax = fmaf(ax, di, bv.x);
    ay = fmaf(ay, di, bv.y);

    if (RELU_OUT) {
        ax = fmaxf(ax, 0.f); ay = fmaxf(ay, 0.f);
    }
    float2 r; r.x = ax; r.y = ay;
    *reinterpret_cast<float2*>(agg + (size_t)node * HID + col) = r;
}

// ---------------- tuple tail ------------------------------------------------
__global__ void cast_ei_kernel(const int* __restrict__ ei,
                               float* __restrict__ o, int E) {
    int i = blockIdx.x * blockDim.x + threadIdx.x;
    if (i >= 2 * E) return;
    int v = (i < E) ? edge_src(ei, i, E) : edge_dst(ei, i - E, E);
    o[i] = (float)v;
}

__global__ void copy_words_kernel(const unsigned int* __restrict__ s,
                                  unsigned int* __restrict__ d, int total) {
    int i = blockIdx.x * blockDim.x + threadIdx.x;
    if (i < total) d[i] = s[i];
}

// ---------------- static side-stream (created once; no device mem) ---------
static cudaStream_t g_s2 = nullptr;
static cudaEvent_t  g_evDet = nullptr;   // prep0 done (dtype flag ready)
static cudaEvent_t  g_evM1  = nullptr;   // gemm1 done
static cudaEvent_t  g_evS2  = nullptr;   // side stream fully done (tail)
static int          g_stream_init = 0;

// ---------------------------------------------------------------------------
extern "C" void kernel_launch(void* const* d_in, const int* in_sizes, int n_in,
                              void* d_out, int out_size) {
    const float* x  = (const float*)d_in[0];
    const int*   ei = (const int*)d_in[1];
    const float* W1 = (const float*)d_in[2];
    const float* b1 = (const float*)d_in[3];
    const float* W2 = (const float*)d_in[4];
    const float* b2 = (const float*)d_in[5];
    float* out = (float*)d_out;

    const int hid = in_sizes[3];                 // 128
    const int K1  = in_sizes[2] / hid;           // 89
    const int n   = in_sizes[0] / K1;            // 50000
    const int E   = in_sizes[1] / 2;             // 800000
    const int NH  = n * hid;

    if (!g_stream_init) {
        g_stream_init = 1;
        if (cudaStreamCreateWithFlags(&g_s2, cudaStreamNonBlocking) != cudaSuccess)
            g_s2 = nullptr;
        if (g_s2) {
            cudaEventCreateWithFlags(&g_evDet, cudaEventDisableTiming);
            cudaEventCreateWithFlags(&g_evM1,  cudaEventDisableTiming);
            cudaEventCreateWithFlags(&g_evS2,  cudaEventDisableTiming);
        }
    }
    const bool fork = (g_s2 != nullptr);
    cudaStream_t sA = 0;
    cudaStream_t sB = fork ? g_s2 : (cudaStream_t)0;

    const int scan_blocks = (n + SCAN_BS - 1) / SCAN_BS;
    const int gemm_blocks = (n + ROWS_PB - 1) / ROWS_PB;
    const int gath_blocks = (int)(((long long)n * 64 + 255) / 256);  // 2 warps/node
    const int rem = out_size - NH;

    // ---- prep0 (zero + dtype detect) ----
    prep0_kernel<<<(n + 255) / 256, 256, 0, sA>>>(ei, E, n);
    if (fork) { cudaEventRecord(g_evDet, sA); cudaStreamWaitEvent(sB, g_evDet, 0); }

    // ---- side stream: GEMM1 (independent of prep) then tuple tail ----
    gemm_kernel<false, 0, 0, false><<<gemm_blocks, 128, 0, sB>>>(x, W1, 0, n, K1);
    if (fork) cudaEventRecord(g_evM1, sB);
    if (rem == 2 * E) {
        cast_ei_kernel<<<(2 * E + 255) / 256, 256, 0, sB>>>(ei, out + NH, E);
    } else if (rem == 4 * E) {
        copy_words_kernel<<<(rem + 255) / 256, 256, 0, sB>>>(
            (const unsigned int*)ei, (unsigned int*)(out + NH), rem);
    }
    if (fork) cudaEventRecord(g_evS2, sB);

    // ---- main stream: degree / dis / scan / CSR fill ----
    count_deg_kernel<<<(E + 255) / 256, 256, 0, sA>>>(ei, E, n);
    dis_scanA_kernel<<<scan_blocks, SCAN_BS, 0, sA>>>(n);
    scan_phaseB<<<1, 512, 0, sA>>>(scan_blocks, n);
    scan_phaseC<<<scan_blocks, SCAN_BS, 0, sA>>>(n);
    fill_csr_kernel<<<(E + 255) / 256, 256, 0, sA>>>(ei, E, n);

    // ---- join gemm1 only (tail keeps running on sB), then serial chain ----
    if (fork) cudaStreamWaitEvent(sA, g_evM1, 0);

    gather_kernel<0, false, false><<<gath_blocks, 256, 0, sA>>>(b1, out, n);
    gemm_kernel<true, 1, 1, true><<<gemm_blocks, 128, 0, sA>>>(nullptr, W2, 0, n, hid);
    gather_kernel<1, true, true><<<gath_blocks, 256, 0, sA>>>(b2, out, n);

    // ---- final join: tail must be complete before graph end ----
    if (fork) cudaStreamWaitEvent(sA, g_evS2, 0);
}

// round 16
// speedup vs baseline: 1.1797x; 1.1797x over previous
#include <cuda_runtime.h>
#include <cuda_fp16.h>
#include <cstdint>

#define MAX_N   50000
#define MAX_E   800000
#define HID     128
#define KCHUNK  32            // smaller chunk -> 24KB smem -> ~9 blocks/SM
#define ROWS_PB 32            // rows per GEMM block (4 warps x 8 rows)
#define SCAN_BS 256

typedef unsigned long long ull;

// ---------------- scratch (device globals; no allocation allowed) ----------
__device__ __align__(16) __half g_h1[MAX_N * HID];    // x @ W1 (fp16, unscaled)
__device__ __align__(16) float  g_agg1[MAX_N * HID];  // layer-1 aggregate (fp32)
__device__ __align__(16) __half g_h2[MAX_N * HID];    // (relu(agg1)@W2)*dis (fp16)
__device__ int   g_deg[MAX_N];
__device__ int   g_off[MAX_N + 1];
__device__ int   g_cnt[MAX_N];
__device__ __align__(16) int g_csr_src[MAX_E];
__device__ float g_dis[MAX_N];
__device__ int   g_bsum[512];
__device__ int   g_is_i64;

// ---------------- prep0: zero counters + dtype detect (fused) --------------
__global__ void prep0_kernel(const int* __restrict__ ei, int E, int n) {
    int i = blockIdx.x * blockDim.x + threadIdx.x;
    if (i < n) { g_deg[i] = 0; g_cnt[i] = 0; }
    if (blockIdx.x == 0) {
        __shared__ int nz;
        if (threadIdx.x == 0) nz = 0;
        __syncthreads();
        int cnt = min(E, 2048);
        for (int j = threadIdx.x; j < cnt; j += blockDim.x)
            if (ei[2 * j + 1] != 0) nz = 1;
        __syncthreads();
        if (threadIdx.x == 0) g_is_i64 = nz ? 0 : 1;
    }
}

__device__ __forceinline__ int edge_src(const int* p, int e, int E) {
    return g_is_i64 ? p[2 * e] : p[e];
}
__device__ __forceinline__ int edge_dst(const int* p, int e, int E) {
    return g_is_i64 ? p[2 * E + 2 * e] : p[E + e];
}

// ---------------- degree count ----------------------------------------------
__global__ void count_deg_kernel(const int* __restrict__ ei, int E, int n) {
    int e = blockIdx.x * blockDim.x + threadIdx.x;
    if (e < E) {
        int dst = edge_dst(ei, e, E);
        if ((unsigned)dst < (unsigned)n) atomicAdd(&g_deg[dst], 1);
    }
}

// ---------------- dis + per-block sums (scan phase A) ------------------------
__global__ void dis_scanA_kernel(int n) {
    __shared__ int s[SCAN_BS];
    int t = threadIdx.x;
    int i = blockIdx.x * SCAN_BS + t;
    int v = (i < n) ? g_deg[i] : 0;
    if (i < n) g_dis[i] = rsqrtf(1.0f + (float)v);
    s[t] = v;
    __syncthreads();
    for (int off = SCAN_BS / 2; off > 0; off >>= 1) {
        if (t < off) s[t] += s[t + off];
        __syncthreads();
    }
    if (t == 0) g_bsum[blockIdx.x] = s[0];
}

// ---------------- fused scan phase C (block offset computed redundantly) ----
__global__ void scanC_kernel(int n) {
    __shared__ int s[SCAN_BS];
    __shared__ int boff_sh;
    int t = threadIdx.x;
    int i = blockIdx.x * SCAN_BS + t;

    // redundant reduce of preceding block sums (<=512 blocks)
    int part = 0;
    for (int j = t; j < blockIdx.x; j += SCAN_BS) part += g_bsum[j];
    s[t] = part;
    __syncthreads();
    for (int off = SCAN_BS / 2; off > 0; off >>= 1) {
        if (t < off) s[t] += s[t + off];
        __syncthreads();
    }
    if (t == 0) boff_sh = s[0];
    __syncthreads();
    int boff = boff_sh;
    __syncthreads();

    // inclusive scan within block
    int v = (i < n) ? g_deg[i] : 0;
    s[t] = v;
    __syncthreads();
    #pragma unroll
    for (int off = 1; off < SCAN_BS; off <<= 1) {
        int add = (t >= off) ? s[t - off] : 0;
        __syncthreads();
        s[t] += add;
        __syncthreads();
    }
    if (i < n) g_off[i] = boff + s[t] - v;       // exclusive
    if (i == n - 1) g_off[n] = boff + s[t];      // total
}

__global__ void fill_csr_kernel(const int* __restrict__ ei, int E, int n) {
    int e = blockIdx.x * blockDim.x + threadIdx.x;
    if (e >= E) return;
    int src = edge_src(ei, e, E);
    int dst = edge_dst(ei, e, E);
    if ((unsigned)src >= (unsigned)n || (unsigned)dst >= (unsigned)n) return;
    int pos = g_off[dst] + atomicAdd(&g_cnt[dst], 1);
    g_csr_src[pos] = src;
}

// ---------------- packed f32x2 FMA helper -----------------------------------
__device__ __forceinline__ void ffma2(ull& acc, ull a, ull b) {
    asm("fma.rn.f32x2 %0, %1, %2, %0;" : "+l"(acc) : "l"(a), "l"(b));
}

// ---------------- GEMM over row range [r_base, r_end), fp16 output ----------
template <bool RELU_IN, int SRC, int DST, bool PRESCALE>
__global__ void gemm_kernel(const float* __restrict__ X,
                            const float* __restrict__ W,
                            int r_base, int r_end, int K) {
    __shared__ __align__(16) float Ws[KCHUNK * HID];        // 16 KB
    __shared__ __align__(16) float2 Xs2[ROWS_PB * KCHUNK];  //  8 KB
    const float* Xp = (SRC == 0) ? X    : g_agg1;
    __half*      Hp = (DST == 0) ? g_h1 : g_h2;

    int t     = threadIdx.x;
    int lane  = t & 31;
    int warp  = t >> 5;
    int wrow0 = warp * 8;
    int r0    = r_base + blockIdx.x * ROWS_PB;

    ull acc0[8], acc1[8];
    #pragma unroll
    for (int r = 0; r < 8; r++) { acc0[r] = 0ull; acc1[r] = 0ull; }

    const ull* Wsu = reinterpret_cast<const ull*>(Ws);
    const ull* Xsu = reinterpret_cast<const ull*>(Xs2);

    for (int k0 = 0; k0 < K; k0 += KCHUNK) {
        int kc = min(KCHUNK, K - k0);
        {
            const float4* Wg = reinterpret_cast<const float4*>(W + (size_t)k0 * HID);
            float4* Wd = reinterpret_cast<float4*>(Ws);
            int nv = kc * HID / 4;
            for (int i = t; i < nv; i += blockDim.x) Wd[i] = Wg[i];
        }
        for (int i = t; i < ROWS_PB * kc; i += blockDim.x) {
            int r = i / kc, k = i % kc;
            float v = (r0 + r < r_end) ? Xp[(size_t)(r0 + r) * K + k0 + k] : 0.0f;
            if (RELU_IN) v = fmaxf(v, 0.0f);
            Xs2[r * KCHUNK + k] = make_float2(v, v);
        }
        __syncthreads();
        for (int k = 0; k < kc; k++) {
            ull w01 = Wsu[(k * HID) / 2 + lane * 2];
            ull w23 = Wsu[(k * HID) / 2 + lane * 2 + 1];
            #pragma unroll
            for (int r = 0; r < 8; r++) {
                ull xv = Xsu[(wrow0 + r) * KCHUNK + k];
                ffma2(acc0[r], xv, w01);
                ffma2(acc1[r], xv, w23);
            }
        }
        __syncthreads();
    }
    #pragma unroll
    for (int r = 0; r < 8; r++) {
        int row = r0 + wrow0 + r;
        if (row < r_end) {
            float d = PRESCALE ? g_dis[row] : 1.0f;
            float2 p0 = *reinterpret_cast<float2*>(&acc0[r]);
            float2 p1 = *reinterpret_cast<float2*>(&acc1[r]);
            __half2 lo = __floats2half2_rn(p0.x * d, p0.y * d);
            __half2 hi = __floats2half2_rn(p1.x * d, p1.y * d);
            uint2 packed;
            packed.x = *reinterpret_cast<unsigned int*>(&lo);
            packed.y = *reinterpret_cast<unsigned int*>(&hi);
            *reinterpret_cast<uint2*>(Hp + (size_t)row * HID + lane * 4) = packed;
        }
    }
}

// ---------------- fp16 row-chunk load helper ---------------------------------
__device__ __forceinline__ float4 ld_h4(const __half* p) {
    uint2 raw = *reinterpret_cast<const uint2*>(p);
    __half2 lo = *reinterpret_cast<__half2*>(&raw.x);
    __half2 hi = *reinterpret_cast<__half2*>(&raw.y);
    float2 f0 = __half22float2(lo);
    float2 f1 = __half22float2(hi);
    float4 r; r.x = f0.x; r.y = f0.y; r.z = f1.x; r.w = f1.y;
    return r;
}

// ---------------- CSR gather (R14: 1 warp/node, fp16 payload) ----------------
template <int SRC, bool RELU_OUT, bool PRESCALED>
__global__ void gather_kernel(const float* __restrict__ b,
                              float* __restrict__ out_ptr, int n) {
    int node = (blockIdx.x * blockDim.x + threadIdx.x) >> 5;
    int lane = threadIdx.x & 31;
    if (node >= n) return;
    const __half* h   = (SRC == 0) ? g_h1   : g_h2;
    float*        agg = (SRC == 0) ? g_agg1 : out_ptr;

    float di  = g_dis[node];
    int   beg = g_off[node];
    int   end = g_off[node + 1];

    const float4 sv = ld_h4(h + (size_t)node * HID + lane * 4);
    float sw = PRESCALED ? 1.0f : di;
    float ax = sv.x * sw, ay = sv.y * sw, az = sv.z * sw, aw = sv.w * sw;

    int j = beg;
    int a_end = min(end, (beg + 3) & ~3);
    for (; j < a_end; j++) {
        int s0 = g_csr_src[j];
        const float4 v0 = ld_h4(h + (size_t)s0 * HID + lane * 4);
        if (PRESCALED) {
            ax += v0.x; ay += v0.y; az += v0.z; aw += v0.w;
        } else {
            float n0 = g_dis[s0];
            ax = fmaf(v0.x, n0, ax); ay = fmaf(v0.y, n0, ay);
            az = fmaf(v0.z, n0, az); aw = fmaf(v0.w, n0, aw);
        }
    }
    for (; j + 4 <= end; j += 4) {
        const int4 iv = *reinterpret_cast<const int4*>(g_csr_src + j);
        int s0 = iv.x, s1 = iv.y, s2 = iv.z, s3 = iv.w;
        const float4 v0 = ld_h4(h + (size_t)s0 * HID + lane * 4);
        const float4 v1 = ld_h4(h + (size_t)s1 * HID + lane * 4);
        const float4 v2 = ld_h4(h + (size_t)s2 * HID + lane * 4);
        const float4 v3 = ld_h4(h + (size_t)s3 * HID + lane * 4);
        if (PRESCALED) {
            ax += v0.x + v1.x + v2.x + v3.x;
            ay += v0.y + v1.y + v2.y + v3.y;
            az += v0.z + v1.z + v2.z + v3.z;
            aw += v0.w + v1.w + v2.w + v3.w;
        } else {
            float n0 = g_dis[s0], n1 = g_dis[s1], n2 = g_dis[s2], n3 = g_dis[s3];
            ax = fmaf(v0.x, n0, ax); ay = fmaf(v0.y, n0, ay);
            az = fmaf(v0.z, n0, az); aw = fmaf(v0.w, n0, aw);
            ax = fmaf(v1.x, n1, ax); ay = fmaf(v1.y, n1, ay);
            az = fmaf(v1.z, n1, az); aw = fmaf(v1.w, n1, aw);
            ax = fmaf(v2.x, n2, ax); ay = fmaf(v2.y, n2, ay);
            az = fmaf(v2.z, n2, az); aw = fmaf(v2.w, n2, aw);
            ax = fmaf(v3.x, n3, ax); ay = fmaf(v3.y, n3, ay);
            az = fmaf(v3.z, n3, az); aw = fmaf(v3.w, n3, aw);
        }
    }
    for (; j < end; j++) {
        int s0 = g_csr_src[j];
        const float4 v0 = ld_h4(h + (size_t)s0 * HID + lane * 4);
        if (PRESCALED) {
            ax += v0.x; ay += v0.y; az += v0.z; aw += v0.w;
        } else {
            float n0 = g_dis[s0];
            ax = fmaf(v0.x, n0, ax); ay = fmaf(v0.y, n0, ay);
            az = fmaf(v0.z, n0, az); aw = fmaf(v0.w, n0, aw);
        }
    }

    const float4 bv = *reinterpret_cast<const float4*>(b + lane * 4);
    ax = fmaf(ax, di, bv.x);
    ay = fmaf(ay, di, bv.y);
    az = fmaf(az, di, bv.z);
    aw = fmaf(aw, di, bv.w);

    if (RELU_OUT) {
        ax = fmaxf(ax, 0.f); ay = fmaxf(ay, 0.f);
        az = fmaxf(az, 0.f); aw = fmaxf(aw, 0.f);
    }
    float4 r; r.x = ax; r.y = ay; r.z = az; r.w = aw;
    *reinterpret_cast<float4*>(agg + (size_t)node * HID + lane * 4) = r;
}

// ---------------- tuple tail ------------------------------------------------
__global__ void cast_ei_kernel(const int* __restrict__ ei,
                               float* __restrict__ o, int E) {
    int i = blockIdx.x * blockDim.x + threadIdx.x;
    if (i >= 2 * E) return;
    int v = (i < E) ? edge_src(ei, i, E) : edge_dst(ei, i - E, E);
    o[i] = (float)v;
}

__global__ void copy_words_kernel(const unsigned int* __restrict__ s,
                                  unsigned int* __restrict__ d, int total) {
    int i = blockIdx.x * blockDim.x + threadIdx.x;
    if (i < total) d[i] = s[i];
}

// ---------------- static side-stream (created once; no device mem) ---------
static cudaStream_t g_s2 = nullptr;
static cudaEvent_t  g_evDet = nullptr;   // prep0 done (dtype flag ready)
static cudaEvent_t  g_evM1  = nullptr;   // gemm1 done
static cudaEvent_t  g_evS2  = nullptr;   // side stream fully done (tail)
static int          g_stream_init = 0;

// ---------------------------------------------------------------------------
extern "C" void kernel_launch(void* const* d_in, const int* in_sizes, int n_in,
                              void* d_out, int out_size) {
    const float* x  = (const float*)d_in[0];
    const int*   ei = (const int*)d_in[1];
    const float* W1 = (const float*)d_in[2];
    const float* b1 = (const float*)d_in[3];
    const float* W2 = (const float*)d_in[4];
    const float* b2 = (const float*)d_in[5];
    float* out = (float*)d_out;

    const int hid = in_sizes[3];                 // 128
    const int K1  = in_sizes[2] / hid;           // 89
    const int n   = in_sizes[0] / K1;            // 50000
    const int E   = in_sizes[1] / 2;             // 800000
    const int NH  = n * hid;

    if (!g_stream_init) {
        g_stream_init = 1;
        if (cudaStreamCreateWithFlags(&g_s2, cudaStreamNonBlocking) != cudaSuccess)
            g_s2 = nullptr;
        if (g_s2) {
            cudaEventCreateWithFlags(&g_evDet, cudaEventDisableTiming);
            cudaEventCreateWithFlags(&g_evM1,  cudaEventDisableTiming);
            cudaEventCreateWithFlags(&g_evS2,  cudaEventDisableTiming);
        }
    }
    const bool fork = (g_s2 != nullptr);
    cudaStream_t sA = 0;
    cudaStream_t sB = fork ? g_s2 : (cudaStream_t)0;

    const int scan_blocks = (n + SCAN_BS - 1) / SCAN_BS;
    const int gemm_blocks = (n + ROWS_PB - 1) / ROWS_PB;
    const int gath_blocks = (int)(((long long)n * 32 + 255) / 256);
    const int rem = out_size - NH;

    // ---- prep0 (zero + dtype detect) ----
    prep0_kernel<<<(n + 255) / 256, 256, 0, sA>>>(ei, E, n);
    if (fork) { cudaEventRecord(g_evDet, sA); cudaStreamWaitEvent(sB, g_evDet, 0); }

    // ---- side stream: GEMM1 (independent of prep) then tuple tail ----
    gemm_kernel<false, 0, 0, false><<<gemm_blocks, 128, 0, sB>>>(x, W1, 0, n, K1);
    if (fork) cudaEventRecord(g_evM1, sB);
    if (rem == 2 * E) {
        cast_ei_kernel<<<(2 * E + 255) / 256, 256, 0, sB>>>(ei, out + NH, E);
    } else if (rem == 4 * E) {
        copy_words_kernel<<<(rem + 255) / 256, 256, 0, sB>>>(
            (const unsigned int*)ei, (unsigned int*)(out + NH), rem);
    }
    if (fork) cudaEventRecord(g_evS2, sB);

    // ---- main stream: degree / dis / fused scan / CSR fill ----
    count_deg_kernel<<<(E + 255) / 256, 256, 0, sA>>>(ei, E, n);
    dis_scanA_kernel<<<scan_blocks, SCAN_BS, 0, sA>>>(n);
    scanC_kernel<<<scan_blocks, SCAN_BS, 0, sA>>>(n);
    fill_csr_kernel<<<(E + 255) / 256, 256, 0, sA>>>(ei, E, n);

    // ---- join gemm1 only (tail keeps running on sB), then serial chain ----
    if (fork) cudaStreamWaitEvent(sA, g_evM1, 0);

    gather_kernel<0, false, false><<<gath_blocks, 256, 0, sA>>>(b1, out, n);
    gemm_kernel<true, 1, 1, true><<<gemm_blocks, 128, 0, sA>>>(nullptr, W2, 0, n, hid);
    gather_kernel<1, true, true><<<gath_blocks, 256, 0, sA>>>(b2, out, n);

    // ---- final join: tail must be complete before graph end ----
    if (fork) cudaStreamWaitEvent(sA, g_evS2, 0);
}